// round 7
// baseline (speedup 1.0000x reference)
#include <cuda_runtime.h>
#include <cstdint>

typedef unsigned long long ULL;

// ---------------- constants ----------------
constexpr int B  = 4;
constexpr int C  = 64;
constexpr int H  = 128;
constexpr int W  = 128;
constexpr int Hp = 130;
constexpr int Wp = 130;
constexpr int O  = 64;
constexpr int N9 = 9;
constexpr int BHW = B * H * W;   // 65536

// fused prep-kernel block ranges
constexpr int NB_OFF = BHW / 256;                 // 256 offset-conv blocks
constexpr int NB_PAD = B * 529;                   // 2116 pad-transpose blocks
constexpr int NB_PW  = (O * C * N9 + 255) / 256;  // 144 weight blocks
constexpr int PREP_SMEM = N9 * C * N9 * 8;        // 41472 B

// k_main smem layout (96 KB total, 2 blocks/SM)
constexpr int SM_X    = 0;        // 65536 : [64 c][256 px] 16B-chunk XOR swizzled
constexpr int SM_WB   = 65536;    // 16384 : W ping-pong, 2 x [16 k][64 o] dup pairs
constexpr int SM_MIDX = 81920;    // 8192  : int4  [2][256]
constexpr int SM_MW   = 90112;    // 8192  : float4[2][256]
constexpr int SM_MAIN = 98304;

// ---------------- scratch (device globals; no allocs) ----------------
__device__ __align__(16) float g_xpad[B * Hp * Wp * C];   // NHWC zero-padded x0
__device__ __align__(16) ULL   g_wTn2[N9 * C * O];        // [n][c][o] -> (w, w) pair
__device__ __align__(16) int4   g_midx[N9 * BHW];         // [n][P] corner offsets
__device__ __align__(16) float4 g_mw[N9 * BHW];           // [n][P] bilinear weights

// ---------------- packed f32x2 helpers ----------------
__device__ __forceinline__ ULL ffma2(ULL a, ULL b, ULL c) {
    ULL d;
    asm("fma.rn.f32x2 %0, %1, %2, %3;" : "=l"(d) : "l"(a), "l"(b), "l"(c));
    return d;
}
__device__ __forceinline__ ULL pack2(float lo, float hi) {
    ULL d;
    asm("mov.b64 %0, {%1, %2};" : "=l"(d) : "f"(lo), "f"(hi));
    return d;
}
__device__ __forceinline__ void unpack2(ULL v, float& lo, float& hi) {
    asm("mov.b64 {%0, %1}, %2;" : "=f"(lo), "=f"(hi) : "l"(v));
}

// ============================================================================
// Fused prep kernel (offset conv + meta | pad/transpose | weight reshuffle)
// ============================================================================
__global__ void __launch_bounds__(256) k_prep(const float* __restrict__ x0,
                                              const float* __restrict__ x1,
                                              const float* __restrict__ p_w,
                                              const float* __restrict__ p_b,
                                              const float* __restrict__ conv_w) {
    extern __shared__ char dsm[];
    int t = threadIdx.x;
    int bid = blockIdx.x;

    if (bid < NB_OFF) {
        // ---------------- offset conv + metadata ----------------
        ULL* wsm = (ULL*)dsm;   // [n][c][kk] paired weights, 41472 B
        for (int e = t; e < N9 * C * N9; e += 256)
            wsm[e] = pack2(p_w[e], p_w[e + 5184]);
        __syncthreads();

        int P = bid * 256 + t;
        int b = P >> 14;
        int rem = P & 16383;
        int i = rem >> 7;
        int j = rem & 127;

        ULL acc[9];
        #pragma unroll
        for (int n = 0; n < 9; n++) acc[n] = pack2(p_b[n], p_b[n + 9]);

        const float* x1b = x1 + (b * C * H * W) + i * W + j;
        bool rok0 = (i > 0), rok2 = (i < H - 1), cok0 = (j > 0), cok2 = (j < W - 1);

        #pragma unroll 2
        for (int c = 0; c < C; c++) {
            const float* xc = x1b + c * (H * W);
            float v[9];
            #pragma unroll
            for (int di = 0; di < 3; di++) {
                bool rok = (di == 0) ? rok0 : ((di == 2) ? rok2 : true);
                const float* xr = xc + (di - 1) * W;
                v[di * 3 + 0] = (rok && cok0) ? xr[-1] : 0.f;
                v[di * 3 + 1] = rok ? xr[0] : 0.f;
                v[di * 3 + 2] = (rok && cok2) ? xr[1] : 0.f;
            }
            ULL vd[9];
            #pragma unroll
            for (int k = 0; k < 9; k++) vd[k] = pack2(v[k], v[k]);
            const ULL* wrow = &wsm[c * N9];
            #pragma unroll
            for (int n = 0; n < 9; n++) {
                const ULL* wn = wrow + n * (C * N9);
                #pragma unroll
                for (int k = 0; k < 9; k++)
                    acc[n] = ffma2(vd[k], wn[k], acc[n]);
            }
        }

        int xb130 = b * 130;
        #pragma unroll
        for (int n = 0; n < 9; n++) {
            float ox, oy;
            unpack2(acc[n], ox, oy);
            float px = (float)(i + n / 3) + ox;
            float py = (float)(j + n % 3) + oy;
            float fx = floorf(px), fy = floorf(py);
            int qltx = max(min((int)fx, Hp - 1), 0);
            int qlty = max(min((int)fy, Wp - 1), 0);
            int qrbx = max(min((int)fx + 1, Hp - 1), 0);
            int qrby = max(min((int)fy + 1, Wp - 1), 0);
            float pxc = fminf(fmaxf(px, 0.f), (float)(Hp - 1));
            float pyc = fminf(fmaxf(py, 0.f), (float)(Wp - 1));
            float ax = 1.f + (float)qltx - pxc;
            float bx = 1.f - (float)qrbx + pxc;
            float ay = 1.f + (float)qlty - pyc;
            float by = 1.f - (float)qrby + pyc;
            int4 idx;
            idx.x = ((xb130 + qltx) * 130 + qlty) * 64;
            idx.y = ((xb130 + qrbx) * 130 + qrby) * 64;
            idx.z = ((xb130 + qltx) * 130 + qrby) * 64;
            idx.w = ((xb130 + qrbx) * 130 + qlty) * 64;
            float4 wv;
            wv.x = ax * ay;
            wv.y = bx * by;
            wv.z = ax * by;
            wv.w = bx * ay;
            g_midx[n * BHW + P] = idx;
            g_mw[n * BHW + P]   = wv;
        }
    } else if (bid < NB_OFF + NB_PAD) {
        // ---------------- pad + transpose ----------------
        float (*tile)[33] = (float(*)[33])dsm;
        int bp = bid - NB_OFF;
        int b  = bp / 529;
        int p0 = (bp - b * 529) * 32;
        int tx = t & 31;
        int ty = t >> 5;

        #pragma unroll
        for (int cc = ty; cc < 64; cc += 8) {
            int p = p0 + tx;
            float v = 0.f;
            if (p < Hp * Wp) {
                int y = p / Wp, x = p - (p / Wp) * Wp;
                if (y >= 1 && y <= H && x >= 1 && x <= W)
                    v = x0[((b * C + cc) * H + (y - 1)) * W + (x - 1)];
            }
            tile[cc][tx] = v;
        }
        __syncthreads();

        int base = (b * Hp * Wp + p0) * 64;
        for (int e = t; e < 32 * 64; e += 256) {
            int pl = e >> 6, c = e & 63;
            if (p0 + pl < Hp * Wp)
                g_xpad[base + pl * 64 + c] = tile[c][pl];
        }
    } else {
        // ---------------- conv_w reshuffle ----------------
        int idx = (bid - NB_OFF - NB_PAD) * 256 + t;
        if (idx < O * C * N9) {
            int o = idx / (C * N9);
            int c = (idx / N9) % C;
            int n = idx % N9;
            float w = conv_w[idx];
            g_wTn2[(n * C + c) * O + o] = pack2(w, w);
        }
    }
}

// ---- GEMM inner chunk: 8 k-steps over W buffer wb, quarter q ----
#define GEMM8(q_, j0_, wb_)                                                     \
    _Pragma("unroll")                                                           \
    for (int kL = (j0_); kL < (j0_) + 8; kL++) {                                \
        int k = (q_) * 16 + kL;                                                 \
        const char* xrow = xoffb + (k << 10);                                   \
        int xk = (k >> 2) & 7;                                                  \
        ulonglong2 xA = *(const ulonglong2*)(xrow + ((lane ^ xk) << 4));        \
        ulonglong2 xB = *(const ulonglong2*)(xrow + (((lane + 32) ^ xk) << 4)); \
        const ULL* wr = wbufs + (wb_) * 1024 + (kL << 6) + (warp << 3);         \
        ulonglong2 w01 = *(const ulonglong2*)(wr + 0);                          \
        ulonglong2 w23 = *(const ulonglong2*)(wr + 2);                          \
        ulonglong2 w45 = *(const ulonglong2*)(wr + 4);                          \
        ulonglong2 w67 = *(const ulonglong2*)(wr + 6);                          \
        acc[0][0] = ffma2(xA.x, w01.x, acc[0][0]);                              \
        acc[0][1] = ffma2(xA.y, w01.x, acc[0][1]);                              \
        acc[0][2] = ffma2(xB.x, w01.x, acc[0][2]);                              \
        acc[0][3] = ffma2(xB.y, w01.x, acc[0][3]);                              \
        acc[1][0] = ffma2(xA.x, w01.y, acc[1][0]);                              \
        acc[1][1] = ffma2(xA.y, w01.y, acc[1][1]);                              \
        acc[1][2] = ffma2(xB.x, w01.y, acc[1][2]);                              \
        acc[1][3] = ffma2(xB.y, w01.y, acc[1][3]);                              \
        acc[2][0] = ffma2(xA.x, w23.x, acc[2][0]);                              \
        acc[2][1] = ffma2(xA.y, w23.x, acc[2][1]);                              \
        acc[2][2] = ffma2(xB.x, w23.x, acc[2][2]);                              \
        acc[2][3] = ffma2(xB.y, w23.x, acc[2][3]);                              \
        acc[3][0] = ffma2(xA.x, w23.y, acc[3][0]);                              \
        acc[3][1] = ffma2(xA.y, w23.y, acc[3][1]);                              \
        acc[3][2] = ffma2(xB.x, w23.y, acc[3][2]);                              \
        acc[3][3] = ffma2(xB.y, w23.y, acc[3][3]);                              \
        acc[4][0] = ffma2(xA.x, w45.x, acc[4][0]);                              \
        acc[4][1] = ffma2(xA.y, w45.x, acc[4][1]);                              \
        acc[4][2] = ffma2(xB.x, w45.x, acc[4][2]);                              \
        acc[4][3] = ffma2(xB.y, w45.x, acc[4][3]);                              \
        acc[5][0] = ffma2(xA.x, w45.y, acc[5][0]);                              \
        acc[5][1] = ffma2(xA.y, w45.y, acc[5][1]);                              \
        acc[5][2] = ffma2(xB.x, w45.y, acc[5][2]);                              \
        acc[5][3] = ffma2(xB.y, w45.y, acc[5][3]);                              \
        acc[6][0] = ffma2(xA.x, w67.x, acc[6][0]);                              \
        acc[6][1] = ffma2(xA.y, w67.x, acc[6][1]);                              \
        acc[6][2] = ffma2(xB.x, w67.x, acc[6][2]);                              \
        acc[6][3] = ffma2(xB.y, w67.x, acc[6][3]);                              \
        acc[7][0] = ffma2(xA.x, w67.y, acc[7][0]);                              \
        acc[7][1] = ffma2(xA.y, w67.y, acc[7][1]);                              \
        acc[7][2] = ffma2(xB.x, w67.y, acc[7][2]);                              \
        acc[7][3] = ffma2(xB.y, w67.y, acc[7][3]);                              \
    }

// ============================================================================
// k_main: 2-row blocks (256 px x 64 o), 256 threads, software-pipelined:
// X split in 4 k-quarters (single buffer, in-place pipeline), W quarter
// ping-pong (2x8KB), meta double-buffered. Per step (n,q): GEMM quarter q of
// tap n overlapped with gather of quarter (q-1)%4 of the next tap.
// ============================================================================
__global__ void __launch_bounds__(256, 2) k_main(float* __restrict__ out) {
    extern __shared__ char dsm[];
    char*   xoffb  = dsm + SM_X;
    ULL*    wbufs  = (ULL*)(dsm + SM_WB);
    int4*   midx_s = (int4*)(dsm + SM_MIDX);
    float4* mw_s   = (float4*)(dsm + SM_MW);

    int t = threadIdx.x;
    int warp = t >> 5;
    int lane = t & 31;
    int bid = blockIdx.x;             // 256 blocks
    int i2 = bid & 63;
    int b  = bid >> 6;
    int pixbase = (b * H + i2 * 2) * W;

    int cqL = t & 3;                  // channel quad within quarter
    int pc  = t >> 2;                 // pixel 16B-chunk (4 px), 0..63

    ULL acc[8][4];
    #pragma unroll
    for (int r = 0; r < 8; r++)
        #pragma unroll
        for (int p = 0; p < 4; p++) acc[r][p] = 0ull;

    // ---------------- prologue ----------------
    midx_s[t] = g_midx[pixbase + t];                  // meta(0) -> buffer 0
    mw_s[t]   = g_mw[pixbase + t];
    {
        const float4* wsrc = (const float4*)g_wTn2;   // W(0, q=0) -> buffer 0
        float4* wdst = (float4*)wbufs;
        wdst[t] = wsrc[t];
        wdst[t + 256] = wsrc[t + 256];
    }
    __syncthreads();

    // gather quarters 0..2 of tap 0 (unpipelined)
    #pragma unroll 1
    for (int gq = 0; gq < 3; gq++) {
        int cq = gq * 4 + cqL;
        int c0 = cq * 4;
        const float* xp = g_xpad + c0;
        float rr[4][4];
        #pragma unroll
        for (int e = 0; e < 4; e++) {
            int px = pc * 4 + e;
            int4   id = midx_s[px];
            float4 g  = mw_s[px];
            float4 v0 = *(const float4*)(xp + id.x);
            float4 v1 = *(const float4*)(xp + id.y);
            float4 v2 = *(const float4*)(xp + id.z);
            float4 v3 = *(const float4*)(xp + id.w);
            rr[e][0] = g.x * v0.x + g.y * v1.x + g.z * v2.x + g.w * v3.x;
            rr[e][1] = g.x * v0.y + g.y * v1.y + g.z * v2.y + g.w * v3.y;
            rr[e][2] = g.x * v0.z + g.y * v1.z + g.z * v2.z + g.w * v3.z;
            rr[e][3] = g.x * v0.w + g.y * v1.w + g.z * v2.w + g.w * v3.w;
        }
        int chunk = pc ^ (cq & 7);
        #pragma unroll
        for (int ch = 0; ch < 4; ch++)
            *(float4*)(xoffb + ((c0 + ch) << 10) + (chunk << 4)) =
                make_float4(rr[0][ch], rr[1][ch], rr[2][ch], rr[3][ch]);
    }
    __syncthreads();

    // ---------------- pipelined steps ----------------
    #pragma unroll 1
    for (int s = 0; s < 36; s++) {
        int n = s >> 2, q = s & 3;
        int wb = s & 1;
        int g_tap = (q == 0) ? n : n + 1;
        int g_q = (q + 3) & 3;
        bool do_g = (g_tap < 9);
        bool do_meta = (q == 0) && (n < 8);

        // prefetch next W quarter (held in regs, STS at step end)
        float4 wn0, wn1;
        if (s < 35) {
            int s1 = s + 1;
            const float4* wsrc = (const float4*)(g_wTn2 + (s1 >> 2) * 4096 + (s1 & 3) * 1024);
            wn0 = wsrc[t];
            wn1 = wsrc[t + 256];
        }
        // prefetch next tap's meta (once per tap)
        int4 mi; float4 mv;
        if (do_meta) {
            mi = g_midx[(n + 1) * BHW + pixbase + t];
            mv = g_mw[(n + 1) * BHW + pixbase + t];
        }

        int mbuf = g_tap & 1;
        int cq = g_q * 4 + cqL;
        int c0 = cq * 4;
        const float* xp = g_xpad + c0;

        // gather half 1: pixels pc*4, pc*4+1 (issue loads before GEMM chunk)
        float4 va0, va1, va2, va3, vb0, vb1, vb2, vb3, ga, gb;
        if (do_g) {
            int px0 = pc * 4;
            int4 ia = midx_s[mbuf * 256 + px0];
            ga = mw_s[mbuf * 256 + px0];
            int4 ib = midx_s[mbuf * 256 + px0 + 1];
            gb = mw_s[mbuf * 256 + px0 + 1];
            va0 = *(const float4*)(xp + ia.x);
            va1 = *(const float4*)(xp + ia.y);
            va2 = *(const float4*)(xp + ia.z);
            va3 = *(const float4*)(xp + ia.w);
            vb0 = *(const float4*)(xp + ib.x);
            vb1 = *(const float4*)(xp + ib.y);
            vb2 = *(const float4*)(xp + ib.z);
            vb3 = *(const float4*)(xp + ib.w);
        }

        GEMM8(q, 0, wb)

        float rr[4][4];
        if (do_g) {
            rr[0][0] = ga.x * va0.x + ga.y * va1.x + ga.z * va2.x + ga.w * va3.x;
            rr[0][1] = ga.x * va0.y + ga.y * va1.y + ga.z * va2.y + ga.w * va3.y;
            rr[0][2] = ga.x * va0.z + ga.y * va1.z + ga.z * va2.z + ga.w * va3.z;
            rr[0][3] = ga.x * va0.w + ga.y * va1.w + ga.z * va2.w + ga.w * va3.w;
            rr[1][0] = gb.x * vb0.x + gb.y * vb1.x + gb.z * vb2.x + gb.w * vb3.x;
            rr[1][1] = gb.x * vb0.y + gb.y * vb1.y + gb.z * vb2.y + gb.w * vb3.y;
            rr[1][2] = gb.x * vb0.z + gb.y * vb1.z + gb.z * vb2.z + gb.w * vb3.z;
            rr[1][3] = gb.x * vb0.w + gb.y * vb1.w + gb.z * vb2.w + gb.w * vb3.w;
            // gather half 2: pixels pc*4+2, pc*4+3
            int px0 = pc * 4;
            int4 ia = midx_s[mbuf * 256 + px0 + 2];
            ga = mw_s[mbuf * 256 + px0 + 2];
            int4 ib = midx_s[mbuf * 256 + px0 + 3];
            gb = mw_s[mbuf * 256 + px0 + 3];
            va0 = *(const float4*)(xp + ia.x);
            va1 = *(const float4*)(xp + ia.y);
            va2 = *(const float4*)(xp + ia.z);
            va3 = *(const float4*)(xp + ia.w);
            vb0 = *(const float4*)(xp + ib.x);
            vb1 = *(const float4*)(xp + ib.y);
            vb2 = *(const float4*)(xp + ib.z);
            vb3 = *(const float4*)(xp + ib.w);
        }

        GEMM8(q, 8, wb)

        if (do_g) {
            rr[2][0] = ga.x * va0.x + ga.y * va1.x + ga.z * va2.x + ga.w * va3.x;
            rr[2][1] = ga.x * va0.y + ga.y * va1.y + ga.z * va2.y + ga.w * va3.y;
            rr[2][2] = ga.x * va0.z + ga.y * va1.z + ga.z * va2.z + ga.w * va3.z;
            rr[2][3] = ga.x * va0.w + ga.y * va1.w + ga.z * va2.w + ga.w * va3.w;
            rr[3][0] = gb.x * vb0.x + gb.y * vb1.x + gb.z * vb2.x + gb.w * vb3.x;
            rr[3][1] = gb.x * vb0.y + gb.y * vb1.y + gb.z * vb2.y + gb.w * vb3.y;
            rr[3][2] = gb.x * vb0.z + gb.y * vb1.z + gb.z * vb2.z + gb.w * vb3.z;
            rr[3][3] = gb.x * vb0.w + gb.y * vb1.w + gb.z * vb2.w + gb.w * vb3.w;
            int chunk = pc ^ (cq & 7);
            #pragma unroll
            for (int ch = 0; ch < 4; ch++)
                *(float4*)(xoffb + ((c0 + ch) << 10) + (chunk << 4)) =
                    make_float4(rr[0][ch], rr[1][ch], rr[2][ch], rr[3][ch]);
        }

        // commit next-W and next-meta to smem
        if (s < 35) {
            float4* wdst = (float4*)(wbufs + (wb ^ 1) * 1024);
            wdst[t] = wn0;
            wdst[t + 256] = wn1;
        }
        if (do_meta) {
            midx_s[((n + 1) & 1) * 256 + t] = mi;
            mw_s[((n + 1) & 1) * 256 + t]   = mv;
        }
        __syncthreads();
    }

    // ---- write out: o = warp*8+r; px lane*4..+3 (row i0) and +128 (row i0+1) ----
    float* ob = out + ((b * O + warp * 8) * H + i2 * 2) * W + lane * 4;
    #pragma unroll
    for (int r = 0; r < 8; r++) {
        float4 pA, pB;
        unpack2(acc[r][0], pA.x, pA.y);
        unpack2(acc[r][1], pA.z, pA.w);
        unpack2(acc[r][2], pB.x, pB.y);
        unpack2(acc[r][3], pB.z, pB.w);
        *(float4*)(ob + r * (H * W))     = pA;
        *(float4*)(ob + r * (H * W) + W) = pB;
    }
}

// ============================================================================
extern "C" void kernel_launch(void* const* d_in, const int* in_sizes, int n_in,
                              void* d_out, int out_size) {
    const float* x0     = (const float*)d_in[0];
    const float* x1     = (const float*)d_in[1];
    const float* p_w    = (const float*)d_in[2];
    const float* p_b    = (const float*)d_in[3];
    const float* conv_w = (const float*)d_in[4];
    float* out = (float*)d_out;

    cudaFuncSetAttribute(k_main, cudaFuncAttributeMaxDynamicSharedMemorySize, SM_MAIN);

    k_prep<<<NB_OFF + NB_PAD + NB_PW, 256, PREP_SMEM>>>(x0, x1, p_w, p_b, conv_w);
    k_main<<<B * H / 2, 256, SM_MAIN>>>(out);
}

// round 8
// speedup vs baseline: 1.1935x; 1.1935x over previous
#include <cuda_runtime.h>
#include <cstdint>

typedef unsigned long long ULL;

// ---------------- constants ----------------
constexpr int B  = 4;
constexpr int C  = 64;
constexpr int H  = 128;
constexpr int W  = 128;
constexpr int Hp = 130;
constexpr int Wp = 130;
constexpr int O  = 64;
constexpr int N9 = 9;
constexpr int BHW = B * H * W;   // 65536

// fused prep-kernel block ranges
constexpr int NB_OFF = BHW / 256;                 // 256 offset-conv blocks
constexpr int NB_PAD = B * 529;                   // 2116 pad-transpose blocks
constexpr int NB_PW  = (O * C * N9 + 255) / 256;  // 144 weight blocks
constexpr int PREP_SMEM = N9 * C * N9 * 8;        // 41472 B

// k_main smem layout (1-row tiles; 72 KB total, 2 blocks/SM, 148 SMs used)
constexpr int SM_W    = 0;        // 32768 : [k][64 o] duplicated pairs
constexpr int SM_X    = 32768;    // 32768 : [64 c][128 px] 16B-chunk XOR swizzled
constexpr int SM_MIDX = 65536;    // 4096  : int4  [2][128]
constexpr int SM_MW   = 69632;    // 4096  : float4[2][128]
constexpr int SM_MAIN = 73728;

// ---------------- scratch (device globals; no allocs) ----------------
__device__ __align__(16) float g_xpad[B * Hp * Wp * C];   // NHWC zero-padded x0
__device__ __align__(16) ULL   g_wTn2[N9 * C * O];        // [n][c][o] -> (w, w) pair
__device__ __align__(16) int4   g_midx[N9 * BHW];         // [n][P] corner offsets
__device__ __align__(16) float4 g_mw[N9 * BHW];           // [n][P] bilinear weights

// ---------------- packed f32x2 helpers ----------------
__device__ __forceinline__ ULL ffma2(ULL a, ULL b, ULL c) {
    ULL d;
    asm("fma.rn.f32x2 %0, %1, %2, %3;" : "=l"(d) : "l"(a), "l"(b), "l"(c));
    return d;
}
__device__ __forceinline__ ULL pack2(float lo, float hi) {
    ULL d;
    asm("mov.b64 %0, {%1, %2};" : "=l"(d) : "f"(lo), "f"(hi));
    return d;
}
__device__ __forceinline__ void unpack2(ULL v, float& lo, float& hi) {
    asm("mov.b64 {%0, %1}, %2;" : "=f"(lo), "=f"(hi) : "l"(v));
}

// 9-tap neighborhood load for the offset conv (predicated at borders)
#define LOAD9(cc_, vv_) {                                         \
    const float* xc_ = x1b + (cc_) * (H * W);                     \
    vv_[0] = (rok0 && cok0) ? xc_[-W - 1] : 0.f;                  \
    vv_[1] = rok0 ? xc_[-W] : 0.f;                                \
    vv_[2] = (rok0 && cok2) ? xc_[-W + 1] : 0.f;                  \
    vv_[3] = cok0 ? xc_[-1] : 0.f;                                \
    vv_[4] = xc_[0];                                              \
    vv_[5] = cok2 ? xc_[1] : 0.f;                                 \
    vv_[6] = (rok2 && cok0) ? xc_[W - 1] : 0.f;                   \
    vv_[7] = rok2 ? xc_[W] : 0.f;                                 \
    vv_[8] = (rok2 && cok2) ? xc_[W + 1] : 0.f;                   \
}

// ============================================================================
// Fused prep kernel (offset conv + meta | pad/transpose | weight reshuffle)
// ============================================================================
__global__ void __launch_bounds__(256) k_prep(const float* __restrict__ x0,
                                              const float* __restrict__ x1,
                                              const float* __restrict__ p_w,
                                              const float* __restrict__ p_b,
                                              const float* __restrict__ conv_w) {
    extern __shared__ char dsm[];
    int t = threadIdx.x;
    int bid = blockIdx.x;

    if (bid < NB_OFF) {
        // ---------------- offset conv + metadata ----------------
        ULL* wsm = (ULL*)dsm;   // [n][c][kk] paired weights, 41472 B
        for (int e = t; e < N9 * C * N9; e += 256)
            wsm[e] = pack2(p_w[e], p_w[e + 5184]);
        __syncthreads();

        int P = bid * 256 + t;
        int b = P >> 14;
        int rem = P & 16383;
        int i = rem >> 7;
        int j = rem & 127;

        ULL acc[9];
        #pragma unroll
        for (int n = 0; n < 9; n++) acc[n] = pack2(p_b[n], p_b[n + 9]);

        const float* x1b = x1 + (b * C * H * W) + i * W + j;
        bool rok0 = (i > 0), rok2 = (i < H - 1), cok0 = (j > 0), cok2 = (j < W - 1);

        // software-pipelined over channels: prefetch c+1's taps during c's FMAs
        float v[9];
        LOAD9(0, v)
        #pragma unroll 1
        for (int c = 0; c < C; c++) {
            float vn[9];
            int cn = (c < C - 1) ? c + 1 : c;
            LOAD9(cn, vn)
            ULL vd[9];
            #pragma unroll
            for (int k = 0; k < 9; k++) vd[k] = pack2(v[k], v[k]);
            const ULL* wrow = &wsm[c * N9];
            #pragma unroll
            for (int n = 0; n < 9; n++) {
                const ULL* wn = wrow + n * (C * N9);
                #pragma unroll
                for (int k = 0; k < 9; k++)
                    acc[n] = ffma2(vd[k], wn[k], acc[n]);
            }
            #pragma unroll
            for (int k = 0; k < 9; k++) v[k] = vn[k];
        }

        int xb130 = b * 130;
        #pragma unroll
        for (int n = 0; n < 9; n++) {
            float ox, oy;
            unpack2(acc[n], ox, oy);
            float px = (float)(i + n / 3) + ox;
            float py = (float)(j + n % 3) + oy;
            float fx = floorf(px), fy = floorf(py);
            int qltx = max(min((int)fx, Hp - 1), 0);
            int qlty = max(min((int)fy, Wp - 1), 0);
            int qrbx = max(min((int)fx + 1, Hp - 1), 0);
            int qrby = max(min((int)fy + 1, Wp - 1), 0);
            float pxc = fminf(fmaxf(px, 0.f), (float)(Hp - 1));
            float pyc = fminf(fmaxf(py, 0.f), (float)(Wp - 1));
            float ax = 1.f + (float)qltx - pxc;
            float bx = 1.f - (float)qrbx + pxc;
            float ay = 1.f + (float)qlty - pyc;
            float by = 1.f - (float)qrby + pyc;
            int4 idx;
            idx.x = ((xb130 + qltx) * 130 + qlty) * 64;
            idx.y = ((xb130 + qrbx) * 130 + qrby) * 64;
            idx.z = ((xb130 + qltx) * 130 + qrby) * 64;
            idx.w = ((xb130 + qrbx) * 130 + qlty) * 64;
            float4 wv;
            wv.x = ax * ay;
            wv.y = bx * by;
            wv.z = ax * by;
            wv.w = bx * ay;
            g_midx[n * BHW + P] = idx;
            g_mw[n * BHW + P]   = wv;
        }
    } else if (bid < NB_OFF + NB_PAD) {
        // ---------------- pad + transpose ----------------
        float (*tile)[33] = (float(*)[33])dsm;
        int bp = bid - NB_OFF;
        int b  = bp / 529;
        int p0 = (bp - b * 529) * 32;
        int tx = t & 31;
        int ty = t >> 5;

        #pragma unroll
        for (int cc = ty; cc < 64; cc += 8) {
            int p = p0 + tx;
            float v = 0.f;
            if (p < Hp * Wp) {
                int y = p / Wp, x = p - (p / Wp) * Wp;
                if (y >= 1 && y <= H && x >= 1 && x <= W)
                    v = x0[((b * C + cc) * H + (y - 1)) * W + (x - 1)];
            }
            tile[cc][tx] = v;
        }
        __syncthreads();

        int base = (b * Hp * Wp + p0) * 64;
        for (int e = t; e < 32 * 64; e += 256) {
            int pl = e >> 6, c = e & 63;
            if (p0 + pl < Hp * Wp)
                g_xpad[base + pl * 64 + c] = tile[c][pl];
        }
    } else {
        // ---------------- conv_w reshuffle ----------------
        int idx = (bid - NB_OFF - NB_PAD) * 256 + t;
        if (idx < O * C * N9) {
            int o = idx / (C * N9);
            int c = (idx / N9) % C;
            int n = idx % N9;
            float w = conv_w[idx];
            g_wTn2[(n * C + c) * O + o] = pack2(w, w);
        }
    }
}

// ============================================================================
// k_main: 1-row blocks (128 px x 64 o), 256 threads, grid 512 (full 148-SM
// coverage), smem-staged double-buffered meta, tap-major gather +
// broadcast-W GEMM. Warp = 8 outputs x 128 px; lane = one 4-px chunk.
// ============================================================================
__global__ void __launch_bounds__(256, 2) k_main(float* __restrict__ out) {
    extern __shared__ char dsm[];
    ULL*    ws2    = (ULL*)(dsm + SM_W);
    char*   xoffb  = dsm + SM_X;
    int4*   midx_s = (int4*)(dsm + SM_MIDX);    // [2][128]
    float4* mw_s   = (float4*)(dsm + SM_MW);    // [2][128]

    int t = threadIdx.x;
    int warp = t >> 5;
    int lane = t & 31;
    int bid = blockIdx.x;             // 512 blocks
    int i = bid & 127;
    int b = bid >> 7;
    int pixbase = (b * H + i) * W;

    int lg = t & 15;                  // gather: channel quad (c = lg*4)
    int hg = t >> 4;                  // gather: 8-px group (px = hg*8..+7)
    int xorc = lg & 7;

    ULL acc[8][2];
    #pragma unroll
    for (int r = 0; r < 8; r++) { acc[r][0] = 0ull; acc[r][1] = 0ull; }

    const float* xb = g_xpad + lg * 4;

    // prologue: stage meta(0) into buffer 0 (half threads idx, half weights)
    if (t < 128) midx_s[t] = g_midx[pixbase + t];
    else         mw_s[t - 128] = g_mw[pixbase + (t - 128)];
    __syncthreads();

    #pragma unroll 1
    for (int n = 0; n < 9; n++) {
        int cur = n & 1, nxt = cur ^ 1;

        // ---- phase 1: stage W(n), prefetch meta(n+1), gather X(n) ----
        {
            const float4* wsrc = (const float4*)(g_wTn2 + n * 4096);
            float4* wdst = (float4*)(dsm + SM_W);
            #pragma unroll
            for (int k2 = 0; k2 < 8; k2++) wdst[t + k2 * 256] = wsrc[t + k2 * 256];
        }
        if (n < 8) {
            if (t < 128) midx_s[nxt * 128 + t] = g_midx[(n + 1) * BHW + pixbase + t];
            else         mw_s[nxt * 128 + (t - 128)] = g_mw[(n + 1) * BHW + pixbase + (t - 128)];
        }

        #pragma unroll 1
        for (int j = 0; j < 2; j++) {
            float rr[4][4];
            #pragma unroll
            for (int jj = 0; jj < 4; jj++) {
                int px = hg * 8 + j * 4 + jj;
                int4   id = midx_s[cur * 128 + px];
                float4 g  = mw_s[cur * 128 + px];
                float4 v0 = *(const float4*)(xb + id.x);
                float4 v1 = *(const float4*)(xb + id.y);
                float4 v2 = *(const float4*)(xb + id.z);
                float4 v3 = *(const float4*)(xb + id.w);
                rr[jj][0] = g.x * v0.x + g.y * v1.x + g.z * v2.x + g.w * v3.x;
                rr[jj][1] = g.x * v0.y + g.y * v1.y + g.z * v2.y + g.w * v3.y;
                rr[jj][2] = g.x * v0.z + g.y * v1.z + g.z * v2.z + g.w * v3.z;
                rr[jj][3] = g.x * v0.w + g.y * v1.w + g.z * v2.w + g.w * v3.w;
            }
            int chunk = (hg * 2 + j) ^ xorc;   // XOR-swizzled 16B chunk (4 px)
            #pragma unroll
            for (int q = 0; q < 4; q++) {
                *(float4*)(xoffb + ((lg * 4 + q) << 9) + (chunk << 4)) =
                    make_float4(rr[0][q], rr[1][q], rr[2][q], rr[3][q]);
            }
        }
        __syncthreads();

        // ---- phase 2: GEMM: acc[o=warp*8+r][px lane*4..+3] += w[o,k]*x[k,px] ----
        #pragma unroll 4
        for (int k = 0; k < 64; k++) {
            int xk = (k >> 2) & 7;
            ulonglong2 xA = *(const ulonglong2*)(xoffb + (k << 9) + ((lane ^ xk) << 4));
            const ULL* wr = ws2 + (k << 6) + (warp << 3);      // warp-uniform
            ulonglong2 w01 = *(const ulonglong2*)(wr + 0);
            ulonglong2 w23 = *(const ulonglong2*)(wr + 2);
            ulonglong2 w45 = *(const ulonglong2*)(wr + 4);
            ulonglong2 w67 = *(const ulonglong2*)(wr + 6);
            acc[0][0] = ffma2(xA.x, w01.x, acc[0][0]);
            acc[0][1] = ffma2(xA.y, w01.x, acc[0][1]);
            acc[1][0] = ffma2(xA.x, w01.y, acc[1][0]);
            acc[1][1] = ffma2(xA.y, w01.y, acc[1][1]);
            acc[2][0] = ffma2(xA.x, w23.x, acc[2][0]);
            acc[2][1] = ffma2(xA.y, w23.x, acc[2][1]);
            acc[3][0] = ffma2(xA.x, w23.y, acc[3][0]);
            acc[3][1] = ffma2(xA.y, w23.y, acc[3][1]);
            acc[4][0] = ffma2(xA.x, w45.x, acc[4][0]);
            acc[4][1] = ffma2(xA.y, w45.x, acc[4][1]);
            acc[5][0] = ffma2(xA.x, w45.y, acc[5][0]);
            acc[5][1] = ffma2(xA.y, w45.y, acc[5][1]);
            acc[6][0] = ffma2(xA.x, w67.x, acc[6][0]);
            acc[6][1] = ffma2(xA.y, w67.x, acc[6][1]);
            acc[7][0] = ffma2(xA.x, w67.y, acc[7][0]);
            acc[7][1] = ffma2(xA.y, w67.y, acc[7][1]);
        }
        __syncthreads();
    }

    // ---- write out: o = warp*8+r; px lane*4..+3 (coalesced) ----
    float* ob = out + ((b * O + warp * 8) * H + i) * W + lane * 4;
    #pragma unroll
    for (int r = 0; r < 8; r++) {
        float4 v;
        unpack2(acc[r][0], v.x, v.y);
        unpack2(acc[r][1], v.z, v.w);
        *(float4*)(ob + r * (H * W)) = v;
    }
}

// ============================================================================
extern "C" void kernel_launch(void* const* d_in, const int* in_sizes, int n_in,
                              void* d_out, int out_size) {
    const float* x0     = (const float*)d_in[0];
    const float* x1     = (const float*)d_in[1];
    const float* p_w    = (const float*)d_in[2];
    const float* p_b    = (const float*)d_in[3];
    const float* conv_w = (const float*)d_in[4];
    float* out = (float*)d_out;

    cudaFuncSetAttribute(k_main, cudaFuncAttributeMaxDynamicSharedMemorySize, SM_MAIN);

    k_prep<<<NB_OFF + NB_PAD + NB_PW, 256, PREP_SMEM>>>(x0, x1, p_w, p_b, conv_w);
    k_main<<<B * H, 256, SM_MAIN>>>(out);
}

// round 9
// speedup vs baseline: 1.2127x; 1.0161x over previous
#include <cuda_runtime.h>
#include <cstdint>

typedef unsigned long long ULL;

// ---------------- constants ----------------
constexpr int B  = 4;
constexpr int C  = 64;
constexpr int H  = 128;
constexpr int W  = 128;
constexpr int Hp = 130;
constexpr int Wp = 130;
constexpr int O  = 64;
constexpr int N9 = 9;
constexpr int BHW = B * H * W;   // 65536

// fused prep-kernel block ranges
constexpr int NB_OFF = BHW / 256;                 // 256 offset-conv blocks
constexpr int NB_PAD = B * 529;                   // 2116 pad-transpose blocks
constexpr int NB_PW  = (O * C * N9 + 255) / 256;  // 144 weight blocks
constexpr int PREP_SMEM = N9 * C * N9 * 8;        // 41472 B

// k_main smem layout (136 KB, 1 block/SM, 512 threads)
constexpr int SM_X    = 0;        // 2 x 32768 : X[buf][64 c][128 px] swizzled
constexpr int SM_WB   = 65536;    // 2 x 32768 : W[buf][64 k][64 o] dup pairs
constexpr int SM_MIDX = 131072;   // 2 x 2048  : int4  [2][128]
constexpr int SM_MW   = 135168;   // 2 x 2048  : float4[2][128]
constexpr int SM_MAIN = 139264;

// ---------------- scratch (device globals; no allocs) ----------------
__device__ __align__(16) float g_xpad[B * Hp * Wp * C];   // NHWC zero-padded x0
__device__ __align__(16) ULL   g_wTn2[N9 * C * O];        // [n][c][o] -> (w, w) pair
__device__ __align__(16) int4   g_midx[N9 * BHW];         // [n][P] corner offsets
__device__ __align__(16) float4 g_mw[N9 * BHW];           // [n][P] bilinear weights

// ---------------- packed f32x2 helpers ----------------
__device__ __forceinline__ ULL ffma2(ULL a, ULL b, ULL c) {
    ULL d;
    asm("fma.rn.f32x2 %0, %1, %2, %3;" : "=l"(d) : "l"(a), "l"(b), "l"(c));
    return d;
}
__device__ __forceinline__ ULL pack2(float lo, float hi) {
    ULL d;
    asm("mov.b64 %0, {%1, %2};" : "=l"(d) : "f"(lo), "f"(hi));
    return d;
}
__device__ __forceinline__ void unpack2(ULL v, float& lo, float& hi) {
    asm("mov.b64 {%0, %1}, %2;" : "=f"(lo), "=f"(hi) : "l"(v));
}

// ============================================================================
// Fused prep kernel (offset conv + meta | pad/transpose | weight reshuffle)
// (offset-conv path reverted to the measured-fastest R6 form)
// ============================================================================
__global__ void __launch_bounds__(256) k_prep(const float* __restrict__ x0,
                                              const float* __restrict__ x1,
                                              const float* __restrict__ p_w,
                                              const float* __restrict__ p_b,
                                              const float* __restrict__ conv_w) {
    extern __shared__ char dsm[];
    int t = threadIdx.x;
    int bid = blockIdx.x;

    if (bid < NB_OFF) {
        // ---------------- offset conv + metadata ----------------
        ULL* wsm = (ULL*)dsm;   // [n][c][kk] paired weights, 41472 B
        for (int e = t; e < N9 * C * N9; e += 256)
            wsm[e] = pack2(p_w[e], p_w[e + 5184]);
        __syncthreads();

        int P = bid * 256 + t;
        int b = P >> 14;
        int rem = P & 16383;
        int i = rem >> 7;
        int j = rem & 127;

        ULL acc[9];
        #pragma unroll
        for (int n = 0; n < 9; n++) acc[n] = pack2(p_b[n], p_b[n + 9]);

        const float* x1b = x1 + (b * C * H * W) + i * W + j;
        bool rok0 = (i > 0), rok2 = (i < H - 1), cok0 = (j > 0), cok2 = (j < W - 1);

        #pragma unroll 2
        for (int c = 0; c < C; c++) {
            const float* xc = x1b + c * (H * W);
            float v[9];
            #pragma unroll
            for (int di = 0; di < 3; di++) {
                bool rok = (di == 0) ? rok0 : ((di == 2) ? rok2 : true);
                const float* xr = xc + (di - 1) * W;
                v[di * 3 + 0] = (rok && cok0) ? xr[-1] : 0.f;
                v[di * 3 + 1] = rok ? xr[0] : 0.f;
                v[di * 3 + 2] = (rok && cok2) ? xr[1] : 0.f;
            }
            ULL vd[9];
            #pragma unroll
            for (int k = 0; k < 9; k++) vd[k] = pack2(v[k], v[k]);
            const ULL* wrow = &wsm[c * N9];
            #pragma unroll
            for (int n = 0; n < 9; n++) {
                const ULL* wn = wrow + n * (C * N9);
                #pragma unroll
                for (int k = 0; k < 9; k++)
                    acc[n] = ffma2(vd[k], wn[k], acc[n]);
            }
        }

        int xb130 = b * 130;
        #pragma unroll
        for (int n = 0; n < 9; n++) {
            float ox, oy;
            unpack2(acc[n], ox, oy);
            float px = (float)(i + n / 3) + ox;
            float py = (float)(j + n % 3) + oy;
            float fx = floorf(px), fy = floorf(py);
            int qltx = max(min((int)fx, Hp - 1), 0);
            int qlty = max(min((int)fy, Wp - 1), 0);
            int qrbx = max(min((int)fx + 1, Hp - 1), 0);
            int qrby = max(min((int)fy + 1, Wp - 1), 0);
            float pxc = fminf(fmaxf(px, 0.f), (float)(Hp - 1));
            float pyc = fminf(fmaxf(py, 0.f), (float)(Wp - 1));
            float ax = 1.f + (float)qltx - pxc;
            float bx = 1.f - (float)qrbx + pxc;
            float ay = 1.f + (float)qlty - pyc;
            float by = 1.f - (float)qrby + pyc;
            int4 idx;
            idx.x = ((xb130 + qltx) * 130 + qlty) * 64;
            idx.y = ((xb130 + qrbx) * 130 + qrby) * 64;
            idx.z = ((xb130 + qltx) * 130 + qrby) * 64;
            idx.w = ((xb130 + qrbx) * 130 + qlty) * 64;
            float4 wv;
            wv.x = ax * ay;
            wv.y = bx * by;
            wv.z = ax * by;
            wv.w = bx * ay;
            g_midx[n * BHW + P] = idx;
            g_mw[n * BHW + P]   = wv;
        }
    } else if (bid < NB_OFF + NB_PAD) {
        // ---------------- pad + transpose ----------------
        float (*tile)[33] = (float(*)[33])dsm;
        int bp = bid - NB_OFF;
        int b  = bp / 529;
        int p0 = (bp - b * 529) * 32;
        int tx = t & 31;
        int ty = t >> 5;

        #pragma unroll
        for (int cc = ty; cc < 64; cc += 8) {
            int p = p0 + tx;
            float v = 0.f;
            if (p < Hp * Wp) {
                int y = p / Wp, x = p - (p / Wp) * Wp;
                if (y >= 1 && y <= H && x >= 1 && x <= W)
                    v = x0[((b * C + cc) * H + (y - 1)) * W + (x - 1)];
            }
            tile[cc][tx] = v;
        }
        __syncthreads();

        int base = (b * Hp * Wp + p0) * 64;
        for (int e = t; e < 32 * 64; e += 256) {
            int pl = e >> 6, c = e & 63;
            if (p0 + pl < Hp * Wp)
                g_xpad[base + pl * 64 + c] = tile[c][pl];
        }
    } else {
        // ---------------- conv_w reshuffle ----------------
        int idx = (bid - NB_OFF - NB_PAD) * 256 + t;
        if (idx < O * C * N9) {
            int o = idx / (C * N9);
            int c = (idx / N9) % C;
            int n = idx % N9;
            float w = conv_w[idx];
            g_wTn2[(n * C + c) * O + o] = pack2(w, w);
        }
    }
}

// producer-side gather of one tap into an X buffer (thread pt in 0..255)
__device__ __forceinline__ void gather_tap(char* xdst, const int4* midx_s,
                                           const float4* mw_s, const float* xb,
                                           int lg, int hg, int xorc) {
    #pragma unroll 1
    for (int j = 0; j < 2; j++) {
        float rr[4][4];
        #pragma unroll
        for (int jj = 0; jj < 4; jj++) {
            int px = hg * 8 + j * 4 + jj;
            int4   id = midx_s[px];
            float4 g  = mw_s[px];
            float4 v0 = *(const float4*)(xb + id.x);
            float4 v1 = *(const float4*)(xb + id.y);
            float4 v2 = *(const float4*)(xb + id.z);
            float4 v3 = *(const float4*)(xb + id.w);
            rr[jj][0] = g.x * v0.x + g.y * v1.x + g.z * v2.x + g.w * v3.x;
            rr[jj][1] = g.x * v0.y + g.y * v1.y + g.z * v2.y + g.w * v3.y;
            rr[jj][2] = g.x * v0.z + g.y * v1.z + g.z * v2.z + g.w * v3.z;
            rr[jj][3] = g.x * v0.w + g.y * v1.w + g.z * v2.w + g.w * v3.w;
        }
        int chunk = (hg * 2 + j) ^ xorc;
        #pragma unroll
        for (int q = 0; q < 4; q++) {
            *(float4*)(xdst + ((lg * 4 + q) << 9) + (chunk << 4)) =
                make_float4(rr[0][q], rr[1][q], rr[2][q], rr[3][q]);
        }
    }
}

// ============================================================================
// k_main: warp-specialized. 512 threads, 1 block/SM (136 KB smem).
//  warps 0-7  (consumers): GEMM tap n from X/W buffer n&1 (R8 GEMM shape).
//  warps 8-15 (producers): stage meta/W(n+1) + gather X(n+1) into buffer nxt.
// One __syncthreads per tap; producer-internal bar.sync(1) meta->gather.
// ============================================================================
__global__ void __launch_bounds__(512, 1) k_main(float* __restrict__ out) {
    extern __shared__ char dsm[];
    char*   xbufs  = dsm + SM_X;
    ULL*    wbufs  = (ULL*)(dsm + SM_WB);
    int4*   midx_s = (int4*)(dsm + SM_MIDX);    // [2][128]
    float4* mw_s   = (float4*)(dsm + SM_MW);    // [2][128]

    int t = threadIdx.x;
    int bid = blockIdx.x;             // 512 blocks
    int i = bid & 127;
    int b = bid >> 7;
    int pixbase = (b * H + i) * W;

    if (t < 256) {
        // ================= CONSUMERS: warps 0-7 =================
        int warp = t >> 5;
        int lane = t & 31;
        ULL acc[8][2];
        #pragma unroll
        for (int r = 0; r < 8; r++) { acc[r][0] = 0ull; acc[r][1] = 0ull; }

        __syncthreads();   // wait for prologue (producers filled buffer 0)

        #pragma unroll 1
        for (int n = 0; n < 9; n++) {
            const char* xb = xbufs + (n & 1) * 32768;
            const ULL*  ws = wbufs + (n & 1) * 4096;
            #pragma unroll 4
            for (int k = 0; k < 64; k++) {
                int xk = (k >> 2) & 7;
                ulonglong2 xA = *(const ulonglong2*)(xb + (k << 9) + ((lane ^ xk) << 4));
                const ULL* wr = ws + (k << 6) + (warp << 3);       // warp-uniform
                ulonglong2 w01 = *(const ulonglong2*)(wr + 0);
                ulonglong2 w23 = *(const ulonglong2*)(wr + 2);
                ulonglong2 w45 = *(const ulonglong2*)(wr + 4);
                ulonglong2 w67 = *(const ulonglong2*)(wr + 6);
                acc[0][0] = ffma2(xA.x, w01.x, acc[0][0]);
                acc[0][1] = ffma2(xA.y, w01.x, acc[0][1]);
                acc[1][0] = ffma2(xA.x, w01.y, acc[1][0]);
                acc[1][1] = ffma2(xA.y, w01.y, acc[1][1]);
                acc[2][0] = ffma2(xA.x, w23.x, acc[2][0]);
                acc[2][1] = ffma2(xA.y, w23.x, acc[2][1]);
                acc[3][0] = ffma2(xA.x, w23.y, acc[3][0]);
                acc[3][1] = ffma2(xA.y, w23.y, acc[3][1]);
                acc[4][0] = ffma2(xA.x, w45.x, acc[4][0]);
                acc[4][1] = ffma2(xA.y, w45.x, acc[4][1]);
                acc[5][0] = ffma2(xA.x, w45.y, acc[5][0]);
                acc[5][1] = ffma2(xA.y, w45.y, acc[5][1]);
                acc[6][0] = ffma2(xA.x, w67.x, acc[6][0]);
                acc[6][1] = ffma2(xA.y, w67.x, acc[6][1]);
                acc[7][0] = ffma2(xA.x, w67.y, acc[7][0]);
                acc[7][1] = ffma2(xA.y, w67.y, acc[7][1]);
            }
            __syncthreads();   // tap boundary: swap buffers
        }

        // write out: o = warp*8+r; px lane*4..+3 (coalesced)
        float* ob = out + ((b * O + warp * 8) * H + i) * W + lane * 4;
        #pragma unroll
        for (int r = 0; r < 8; r++) {
            float4 v;
            unpack2(acc[r][0], v.x, v.y);
            unpack2(acc[r][1], v.z, v.w);
            *(float4*)(ob + r * (H * W)) = v;
        }
    } else {
        // ================= PRODUCERS: warps 8-15 =================
        int pt = t - 256;                  // 0..255
        int lg = pt & 15;                  // channel quad (c = lg*4)
        int hg = pt >> 4;                  // 8-px group
        int xorc = lg & 7;
        const float* xb = g_xpad + lg * 4;

        // ---- prologue: meta(0), W(0), gather(0) -> buffer 0 ----
        if (pt < 128) midx_s[pt] = g_midx[pixbase + pt];
        else          mw_s[pt - 128] = g_mw[pixbase + (pt - 128)];
        {
            const float4* wsrc = (const float4*)g_wTn2;
            float4* wdst = (float4*)wbufs;
            #pragma unroll
            for (int k2 = 0; k2 < 8; k2++) wdst[pt + k2 * 256] = wsrc[pt + k2 * 256];
        }
        asm volatile("bar.sync 1, 256;" ::: "memory");   // meta visible to producers
        gather_tap(xbufs, midx_s, mw_s, xb, lg, hg, xorc);
        __syncthreads();

        #pragma unroll 1
        for (int n = 0; n < 9; n++) {
            if (n < 8) {
                int nxt = (n + 1) & 1;
                // stage meta(n+1)
                if (pt < 128) midx_s[nxt * 128 + pt] = g_midx[(n + 1) * BHW + pixbase + pt];
                else          mw_s[nxt * 128 + (pt - 128)] = g_mw[(n + 1) * BHW + pixbase + (pt - 128)];
                // stage W(n+1)
                {
                    const float4* wsrc = (const float4*)(g_wTn2 + (n + 1) * 4096);
                    float4* wdst = (float4*)(wbufs + nxt * 4096);
                    #pragma unroll
                    for (int k2 = 0; k2 < 8; k2++) wdst[pt + k2 * 256] = wsrc[pt + k2 * 256];
                }
                asm volatile("bar.sync 1, 256;" ::: "memory");
                // gather X(n+1)
                gather_tap(xbufs + nxt * 32768, midx_s + nxt * 128, mw_s + nxt * 128,
                           xb, lg, hg, xorc);
            }
            __syncthreads();   // tap boundary
        }
    }
}

// ============================================================================
extern "C" void kernel_launch(void* const* d_in, const int* in_sizes, int n_in,
                              void* d_out, int out_size) {
    const float* x0     = (const float*)d_in[0];
    const float* x1     = (const float*)d_in[1];
    const float* p_w    = (const float*)d_in[2];
    const float* p_b    = (const float*)d_in[3];
    const float* conv_w = (const float*)d_in[4];
    float* out = (float*)d_out;

    cudaFuncSetAttribute(k_main, cudaFuncAttributeMaxDynamicSharedMemorySize, SM_MAIN);

    k_prep<<<NB_OFF + NB_PAD + NB_PW, 256, PREP_SMEM>>>(x0, x1, p_w, p_b, conv_w);
    k_main<<<B * H, 512, SM_MAIN>>>(out);
}